// round 11
// baseline (speedup 1.0000x reference)
#include <cuda_runtime.h>
#include <cuda_fp16.h>
#include <cstdint>

// ============================================================================
// CAAN rank-gated attention (sm_100 base: mma.sync fp16 + cp.async):
//   Sf = fp16(S); f[i] = S[i].u + c (fused into convS, fp32)
//   Q,K = fp16( S Wq^T/Wk^T + b )  via single-product fp16 HMMA
//   gate2[d] = log2(e)/sqrt(128) * sigmoid(rank_emb[d].wL+bL)
//   p_ij = exp2( gate2[|ri-rj|/4] * (q_i.k_j) )   (no-max softmax; |arg| small)
//   out_i = sigmoid( (sum_j p f_j)/(sum_j p) + wf_b )
// R10 post-mortem: attn now issue/epilogue-bound (tensor 28%, issue 46%).
// R11: 4Mx2N warps, Q fragments cached in regs (1 prologue load), 64-key
// half-tile ping-pong acc (32 floats total, no R8-style spill), epilogue
// interleaved into next half-tile's MMA window, pre-scaled ranks, no clamp
// (ranks<4096 => index<1024 always).
// ============================================================================

#define N_ASSETS 4096
#define D_MODEL  512
#define DK       128
#define NUM_EMB  1024
#define NCHUNK   4
#define KEYS_PER_CHUNK (N_ASSETS / NCHUNK)
#define GATE_MUL    0.1275174677682657f      // (1/sqrt(128)) * log2(e)

typedef unsigned long long ull;

// --------------------------- scratch (no allocs) ----------------------------
__device__ __align__(16) __half d_Sf[N_ASSETS * D_MODEL];
__device__ __align__(16) __half d_Wf[256 * D_MODEL];   // rows 0-127 Wq, 128-255 Wk
__device__ __align__(16) __half d_Q[N_ASSETS * DK];
__device__ __align__(16) __half d_K[N_ASSETS * DK];
__device__ float d_f[N_ASSETS];
__device__ float d_u[D_MODEL + 1];
__device__ float d_gate[NUM_EMB];            // premultiplied by GATE_MUL
__device__ float d_pl[NCHUNK * N_ASSETS];
__device__ float d_pw[NCHUNK * N_ASSETS];

// --------------------------- mma/ldsm/cp.async helpers -----------------------
__device__ __forceinline__ uint32_t smem_u32(const void* p) {
    uint32_t a;
    asm("{ .reg .u64 t; cvta.to.shared.u64 t, %1; cvt.u32.u64 %0, t; }"
        : "=r"(a) : "l"(p));
    return a;
}
__device__ __forceinline__ void ldsm4(uint32_t* r, uint32_t addr) {
    asm volatile("ldmatrix.sync.aligned.m8n8.x4.shared.b16 {%0,%1,%2,%3}, [%4];"
                 : "=r"(r[0]), "=r"(r[1]), "=r"(r[2]), "=r"(r[3]) : "r"(addr));
}
__device__ __forceinline__ void mma_f16(float* c, const uint32_t* a, const uint32_t* b) {
    asm volatile(
        "mma.sync.aligned.m16n8k16.row.col.f32.f16.f16.f32 "
        "{%0,%1,%2,%3}, {%4,%5,%6,%7}, {%8,%9}, {%0,%1,%2,%3};"
        : "+f"(c[0]), "+f"(c[1]), "+f"(c[2]), "+f"(c[3])
        : "r"(a[0]), "r"(a[1]), "r"(a[2]), "r"(a[3]), "r"(b[0]), "r"(b[1]));
}
__device__ __forceinline__ void cp16(uint32_t dst, const void* src) {
    asm volatile("cp.async.cg.shared.global [%0], [%1], 16;" :: "r"(dst), "l"(src));
}
__device__ __forceinline__ void cp4(uint32_t dst, const void* src) {
    asm volatile("cp.async.ca.shared.global [%0], [%1], 4;" :: "r"(dst), "l"(src));
}
#define CP_COMMIT() asm volatile("cp.async.commit_group;" ::: "memory")
#define CP_WAIT0()  asm volatile("cp.async.wait_group 0;" ::: "memory")
#define CP_WAIT1()  asm volatile("cp.async.wait_group 1;" ::: "memory")

// XOR swizzle of 16B-chunk index within a 256B row (16 chunks)
__device__ __forceinline__ int swz(int chunk, int row) {
    return (chunk & 8) | ((chunk ^ row) & 7);
}

// ============================================================================
// prep: gate (b 0-3), u (b 4-19), c (b 20), W fp16 convert (b 21-84)
// ============================================================================
__global__ void prep_kernel(const float* __restrict__ rank_emb,
                            const float* __restrict__ wL_w,
                            const float* __restrict__ wL_b,
                            const float* __restrict__ Wv_w,
                            const float* __restrict__ wf_w,
                            const float* __restrict__ Wv_b,
                            const float* __restrict__ Wq_w,
                            const float* __restrict__ Wk_w) {
    int b = blockIdx.x, t = threadIdx.x;
    if (b < 4) {
        int d = b * 256 + t;
        float s = wL_b[0];
        #pragma unroll 8
        for (int e = 0; e < 32; e++) s += rank_emb[d * 32 + e] * wL_w[e];
        d_gate[d] = GATE_MUL / (1.0f + __expf(-s));
    } else if (b < 20) {
        int b2 = b - 4;
        int mloc = t & 31, oo = t >> 5;
        int m = b2 * 32 + mloc;
        float s = 0.f;
        #pragma unroll 4
        for (int o = oo; o < D_MODEL; o += 8) s += Wv_w[o * D_MODEL + m] * wf_w[o];
        __shared__ float red[256];
        red[t] = s; __syncthreads();
        if (t < 32) {
            float x = red[t];
            #pragma unroll
            for (int i = 1; i < 8; i++) x += red[t + 32 * i];
            d_u[m] = x;
        }
    } else if (b == 20) {
        __shared__ float red[256];
        float s = 0.f;
        for (int o = t; o < D_MODEL; o += 256) s += wf_w[o] * Wv_b[o];
        red[t] = s; __syncthreads();
        for (int st = 128; st > 0; st >>= 1) {
            if (t < st) red[t] += red[t + st];
            __syncthreads();
        }
        if (t == 0) d_u[D_MODEL] = red[0];
    } else {
        int g0 = (b - 21) * 2048 + t * 8;
        #pragma unroll
        for (int j = 0; j < 2; j++) {
            float4 v = (g0 + 4 * j < 65536)
                ? *(const float4*)(Wq_w + g0 + 4 * j)
                : *(const float4*)(Wk_w + g0 + 4 * j - 65536);
            __half2* dst = (__half2*)(d_Wf + g0 + 4 * j);
            dst[0] = __floats2half2_rn(v.x, v.y);
            dst[1] = __floats2half2_rn(v.z, v.w);
        }
    }
}

// ============================================================================
// convS: S -> fp16 AND f[i] = S[i].u + c (one pass)
// ============================================================================
__global__ void __launch_bounds__(256) convS_kernel(const float* __restrict__ S) {
    __shared__ float u_s[D_MODEL];
    int tid = threadIdx.x, w = tid >> 5, lane = tid & 31;
    #pragma unroll
    for (int t = 0; t < 2; t++) u_s[tid + 256 * t] = d_u[tid + 256 * t];
    __syncthreads();
    float c = d_u[D_MODEL];

    int rbase = blockIdx.x * 32 + w * 4;
    #pragma unroll
    for (int rr = 0; rr < 4; rr++) {
        int row = rbase + rr;
        const float2* src = (const float2*)(S + (size_t)row * D_MODEL);
        __half2* dst = (__half2*)(d_Sf + (size_t)row * D_MODEL);
        float s = 0.f;
        #pragma unroll
        for (int t = 0; t < 8; t++) {
            int e2 = lane + 32 * t;
            float2 v = src[e2];
            s += v.x * u_s[2 * e2] + v.y * u_s[2 * e2 + 1];
            dst[e2] = __floats2half2_rn(v.x, v.y);
        }
        #pragma unroll
        for (int st = 16; st > 0; st >>= 1)
            s += __shfl_xor_sync(0xffffffffu, s, st);
        if (lane == 0) d_f[row] = s + c;
    }
}

// ============================================================================
// proj_mma: Q/K = fp16( S @ W^T + b ) single-product fp16 HMMA, 2-stage pipe.
// grid (64 M-tiles of 64 rows, 2 = {Q,K}), 256 thr = 8 warps (2M x 4N).
// ============================================================================
#define PJ_BIAS 0           // 512B
#define PJ_STG  1024        // stage stride 49152: S 16K | W 32K
#define PJ_S    0
#define PJ_W    16384
#define PJ_TOTAL (1024 + 2 * 49152)

__device__ __forceinline__ void pj_copy_stage(uint32_t stg, int mbase, int by, int kc) {
    int tid = threadIdx.x;
    #pragma unroll
    for (int i = 0; i < 4; i++) {
        int idx = tid + 256 * i;
        int row = idx >> 4, c = idx & 15;
        const __half* g = d_Sf + (size_t)(mbase + row) * D_MODEL + kc * 128 + c * 8;
        cp16(stg + PJ_S + row * 256 + swz(c, row) * 16, g);
    }
    #pragma unroll
    for (int i = 0; i < 8; i++) {
        int idx = tid + 256 * i;
        int row = idx >> 4, c = idx & 15;
        const __half* g = d_Wf + (size_t)(by * 128 + row) * D_MODEL + kc * 128 + c * 8;
        cp16(stg + PJ_W + row * 256 + swz(c, row) * 16, g);
    }
}

__global__ void __launch_bounds__(256, 1) proj_mma_kernel(
    const float* __restrict__ Wq_b, const float* __restrict__ Wk_b) {
    extern __shared__ __align__(1024) char smem[];
    uint32_t sb = smem_u32(smem);
    float* bias_s = (float*)(smem + PJ_BIAS);

    int tid = threadIdx.x;
    int w = tid >> 5, lane = tid & 31;
    int wm = w >> 2, wn = w & 3;
    int mbase = blockIdx.x * 64;
    int by = blockIdx.y;                 // 0 = Q, 1 = K

    if (tid < 128) bias_s[tid] = (by ? Wk_b : Wq_b)[tid];

    float acc[2][4][4];
    #pragma unroll
    for (int mi = 0; mi < 2; mi++)
        #pragma unroll
        for (int nf = 0; nf < 4; nf++)
            #pragma unroll
            for (int e = 0; e < 4; e++) acc[mi][nf][e] = 0.f;

    int a_row  = lane & 15, a_hi = lane >> 4;
    int b_nloc = (lane & 7) | ((lane >> 1) & 8);
    int b_hi   = (lane >> 3) & 1;

    pj_copy_stage(sb + PJ_STG, mbase, by, 0);
    CP_COMMIT();

    for (int kc = 0; kc < 4; kc++) {
        uint32_t stg = sb + PJ_STG + (kc & 1) * 49152;
        if (kc < 3) {
            pj_copy_stage(sb + PJ_STG + ((kc + 1) & 1) * 49152, mbase, by, kc + 1);
            CP_COMMIT();
            CP_WAIT1();
        } else {
            CP_WAIT0();
        }
        __syncthreads();

        #pragma unroll
        for (int ks = 0; ks < 8; ks++) {
            uint32_t Bf[2][4];
            int cB = 2 * ks + b_hi;
            #pragma unroll
            for (int np = 0; np < 2; np++) {
                int nrow = wn * 32 + np * 16 + b_nloc;
                ldsm4(Bf[np], stg + PJ_W + nrow * 256 + swz(cB, nrow) * 16);
            }
            #pragma unroll
            for (int mi = 0; mi < 2; mi++) {
                uint32_t Af[4];
                int qrow = wm * 32 + mi * 16 + a_row;
                int cA = 2 * ks + a_hi;
                ldsm4(Af, stg + PJ_S + qrow * 256 + swz(cA, qrow) * 16);
                #pragma unroll
                for (int nf = 0; nf < 4; nf++)
                    mma_f16(acc[mi][nf], Af, &Bf[nf >> 1][(nf & 1) * 2]);
            }
        }
        __syncthreads();
    }

    __half* OUT = by ? d_K : d_Q;
    #pragma unroll
    for (int mi = 0; mi < 2; mi++)
        #pragma unroll
        for (int nf = 0; nf < 4; nf++)
            #pragma unroll
            for (int hrow = 0; hrow < 2; hrow++) {
                int row = mbase + wm * 32 + mi * 16 + (lane >> 2) + 8 * hrow;
                int col = wn * 32 + nf * 8 + 2 * (lane & 3);
                float v0 = acc[mi][nf][2 * hrow]     + bias_s[col];
                float v1 = acc[mi][nf][2 * hrow + 1] + bias_s[col + 1];
                *(__half2*)(OUT + (size_t)row * DK + col) = __floats2half2_rn(v0, v1);
            }
}

// ============================================================================
// attn: grid (64 qblocks of 64 rows, 4 chunks), 256 thr = 8 warps (4M x 2N),
// warp tile 16 rows x 32 cols per 64-key half-tile. Q fragments cached in
// registers (loaded once); half-tile ping-pong acc (2 x 16 floats) with
// epilogue(ht-1) interleaved into MMA(ht). rk/fk 4-slot ring.
// ============================================================================
#define SM_GATE  0          // 4096
#define SM_RK    4096       // float[4][128] ring = 2048
#define SM_FK    6144       // float[4][128] ring = 2048
#define SM_PL    8192       // float[2][64] = 512
#define SM_PW    8704       // 512
#define SM_Q     9216       // 16384
#define SM_K     25600      // 2 x 32768
#define SMEM_TOTAL 91136

__device__ __forceinline__ void cp_tile128(const __half* __restrict__ g,
                                           uint32_t st_base) {
    int tid = threadIdx.x;
    #pragma unroll
    for (int i = 0; i < 8; i++) {
        int idx = tid + 256 * i;
        int row = idx >> 4, c = idx & 15;
        cp16(st_base + row * 256 + swz(c, row) * 16, (const char*)g + row * 256 + c * 16);
    }
}
__device__ __forceinline__ void cp_tile64(const __half* __restrict__ g,
                                          uint32_t st_base) {
    int tid = threadIdx.x;
    #pragma unroll
    for (int i = 0; i < 4; i++) {
        int idx = tid + 256 * i;
        int row = idx >> 4, c = idx & 15;
        cp16(st_base + row * 256 + swz(c, row) * 16, (const char*)g + row * 256 + c * 16);
    }
}

__global__ void __launch_bounds__(256, 2) attn_kernel(const float* __restrict__ ranks) {
    extern __shared__ __align__(1024) char smem[];
    float* gate_s = (float*)(smem + SM_GATE);
    float* rk_s   = (float*)(smem + SM_RK);   // [4][128] ring
    float* fk_s   = (float*)(smem + SM_FK);
    float* pl_s   = (float*)(smem + SM_PL);   // [2][64]
    float* pw_s   = (float*)(smem + SM_PW);
    uint32_t sb = smem_u32(smem);

    int tid = threadIdx.x;
    int w = tid >> 5, lane = tid & 31;
    int wm = w >> 1, wn = w & 1;          // 4M x 2N warp grid
    int qbase = blockIdx.x * 64;
    int cbase = blockIdx.y * KEYS_PER_CHUNK;

    #pragma unroll
    for (int t = 0; t < 4; t++) gate_s[tid + 256 * t] = d_gate[tid + 256 * t];

    cp_tile64(d_Q + (size_t)qbase * DK, sb + SM_Q);
    cp_tile128(d_K + (size_t)cbase * DK, sb + SM_K);
    if (tid < 128) {
        cp4(sb + SM_RK + tid * 4, ranks + cbase + tid);
        cp4(sb + SM_FK + tid * 4, d_f + cbase + tid);
    }
    CP_COMMIT();

    // per-thread query rows (2): row = wm*16 + (lane>>2) + 8*s ; pre-scaled
    float rq2[2];
    #pragma unroll
    for (int s = 0; s < 2; s++)
        rq2[s] = ranks[qbase + wm * 16 + (lane >> 2) + 8 * s] * 0.25f;

    float l2[2] = {0.f, 0.f}, w2[2] = {0.f, 0.f};
    float acc[2][16];
    #pragma unroll
    for (int ps = 0; ps < 2; ps++)
        #pragma unroll
        for (int e = 0; e < 16; e++) acc[ps][e] = 0.f;

    int a_row  = lane & 15, a_hi = lane >> 4;
    int b_nloc = (lane & 7) | ((lane >> 1) & 8);
    int b_hi   = (lane >> 3) & 1;
    int ccl    = 2 * (lane & 3);

    CP_WAIT0();
    __syncthreads();

    // ---- cache Q fragments in registers (reused for all 16 half-tiles) ----
    uint32_t Af[8][4];
    #pragma unroll
    for (int ks = 0; ks < 8; ks++) {
        int qrow = wm * 16 + a_row;
        int cA = 2 * ks + a_hi;
        ldsm4(Af[ks], sb + SM_Q + qrow * 256 + swz(cA, qrow) * 16);
    }

    for (int kt = 0; kt < 8; kt++) {
        uint32_t Kb = sb + SM_K + (kt & 1) * 32768;

        // prefetch K tile kt+1 (buffer (kt+1)&1, rk/fk ring slot (kt+1)&3)
        if (kt < 7) {
            int kb = cbase + (kt + 1) * 128;
            int nb = (kt + 1) & 1, ns = (kt + 1) & 3;
            cp_tile128(d_K + (size_t)kb * DK, sb + SM_K + nb * 32768);
            if (tid < 128) {
                cp4(sb + SM_RK + (ns * 128 + tid) * 4, ranks + kb + tid);
                cp4(sb + SM_FK + (ns * 128 + tid) * 4, d_f + kb + tid);
            }
            CP_COMMIT();
        }

        #pragma unroll
        for (int h = 0; h < 2; h++) {
            int ht = 2 * kt + h;
            float* cacc = acc[ht & 1];

            // ---- MMA for half-tile ht (64 keys at cols h*64..h*64+63) ----
            #pragma unroll
            for (int ks = 0; ks < 8; ks++) {
                uint32_t Bf[2][4];
                int cB = 2 * ks + b_hi;
                #pragma unroll
                for (int np = 0; np < 2; np++) {
                    int nrow = h * 64 + wn * 32 + np * 16 + b_nloc;
                    ldsm4(Bf[np], Kb + nrow * 256 + swz(cB, nrow) * 16);
                }
                #pragma unroll
                for (int nf = 0; nf < 4; nf++)
                    mma_f16(cacc + nf * 4, Af[ks], &Bf[nf >> 1][(nf & 1) * 2]);
            }

            // ---- interleaved epilogue for half-tile ht-1 ----
            if (ht > 0) {
                int pt = ht - 1;
                int pkt = pt >> 1, phh = pt & 1;
                int slot = pkt & 3;
                float* pacc = acc[pt & 1];
                float rk8[8], fk8[8];
                #pragma unroll
                for (int nf = 0; nf < 4; nf++)
                    #pragma unroll
                    for (int hh = 0; hh < 2; hh++) {
                        int c = slot * 128 + phh * 64 + wn * 32 + nf * 8 + ccl + hh;
                        rk8[nf * 2 + hh] = rk_s[c] * 0.25f;
                        fk8[nf * 2 + hh] = fk_s[c];
                    }
                #pragma unroll
                for (int nf = 0; nf < 4; nf++)
                    #pragma unroll
                    for (int e = 0; e < 4; e++) {
                        int s = e >> 1;
                        int ci = nf * 2 + (e & 1);
                        int di = __float2int_rd(fabsf(rq2[s] - rk8[ci]));
                        float pr = exp2f(gate_s[di] * pacc[nf * 4 + e]);
                        l2[s] += pr;
                        w2[s] += pr * fk8[ci];
                        pacc[nf * 4 + e] = 0.f;
                    }
            }
        }

        if (kt < 7) {
            CP_WAIT0();
            __syncthreads();   // tile kt+1 ready; all warps done with buf kt
        }
    }

    // ---- tail epilogue: half-tile 15 (acc set 1, ring slot 3, h=1) ----
    {
        float* pacc = acc[1];
        float rk8[8], fk8[8];
        #pragma unroll
        for (int nf = 0; nf < 4; nf++)
            #pragma unroll
            for (int hh = 0; hh < 2; hh++) {
                int c = 3 * 128 + 64 + wn * 32 + nf * 8 + ccl + hh;
                rk8[nf * 2 + hh] = rk_s[c] * 0.25f;
                fk8[nf * 2 + hh] = fk_s[c];
            }
        #pragma unroll
        for (int nf = 0; nf < 4; nf++)
            #pragma unroll
            for (int e = 0; e < 4; e++) {
                int s = e >> 1;
                int ci = nf * 2 + (e & 1);
                int di = __float2int_rd(fabsf(rq2[s] - rk8[ci]));
                float pr = exp2f(gate_s[di] * pacc[nf * 4 + e]);
                l2[s] += pr;
                w2[s] += pr * fk8[ci];
            }
    }

    // quad reduce (4 lanes share a row), then across 2 N-warps via smem
    #pragma unroll
    for (int s = 0; s < 2; s++) {
        #pragma unroll
        for (int st = 1; st < 4; st <<= 1) {
            l2[s] += __shfl_xor_sync(0xffffffffu, l2[s], st);
            w2[s] += __shfl_xor_sync(0xffffffffu, w2[s], st);
        }
    }
    if ((lane & 3) == 0) {
        #pragma unroll
        for (int s = 0; s < 2; s++) {
            int row = wm * 16 + (lane >> 2) + 8 * s;
            pl_s[wn * 64 + row] = l2[s];
            pw_s[wn * 64 + row] = w2[s];
        }
    }
    __syncthreads();
    if (tid < 64) {
        float L = pl_s[tid] + pl_s[64 + tid];
        float W = pw_s[tid] + pw_s[64 + tid];
        int idx = blockIdx.y * N_ASSETS + qbase + tid;
        d_pl[idx] = L;
        d_pw[idx] = W;
    }
}

// ============================================================================
// combine: merge NCHUNK partial sums, final sigmoid
// ============================================================================
__global__ void combine_kernel(const float* __restrict__ wf_b, float* __restrict__ out) {
    int i = blockIdx.x * blockDim.x + threadIdx.x;
    if (i >= N_ASSETS) return;
    float L = 0.f, W = 0.f;
    #pragma unroll
    for (int c = 0; c < NCHUNK; c++) {
        L += d_pl[c * N_ASSETS + i];
        W += d_pw[c * N_ASSETS + i];
    }
    float z = W / L + wf_b[0];
    out[i] = 1.0f / (1.0f + __expf(-z));
}

// ============================================================================
// launch
// ============================================================================
extern "C" void kernel_launch(void* const* d_in, const int* in_sizes, int n_in,
                              void* d_out, int out_size) {
    const float* S        = (const float*)d_in[0];
    const float* ranks    = (const float*)d_in[1];
    const float* Wq_w     = (const float*)d_in[2];
    const float* Wq_b     = (const float*)d_in[3];
    const float* Wk_w     = (const float*)d_in[4];
    const float* Wk_b     = (const float*)d_in[5];
    const float* Wv_w     = (const float*)d_in[6];
    const float* Wv_b     = (const float*)d_in[7];
    const float* rank_emb = (const float*)d_in[8];
    const float* wL_w     = (const float*)d_in[9];
    const float* wL_b     = (const float*)d_in[10];
    const float* wf_w     = (const float*)d_in[11];
    const float* wf_b     = (const float*)d_in[12];
    float* out = (float*)d_out;

    static int attr_set = 0;
    if (!attr_set) {
        cudaFuncSetAttribute(attn_kernel,
                             cudaFuncAttributeMaxDynamicSharedMemorySize, SMEM_TOTAL);
        cudaFuncSetAttribute(proj_mma_kernel,
                             cudaFuncAttributeMaxDynamicSharedMemorySize, PJ_TOTAL);
        attr_set = 1;
    }

    prep_kernel<<<85, 256>>>(rank_emb, wL_w, wL_b, Wv_w, wf_w, Wv_b, Wq_w, Wk_w);
    convS_kernel<<<128, 256>>>(S);
    proj_mma_kernel<<<dim3(64, 2), 256, PJ_TOTAL>>>(Wq_b, Wk_b);
    attn_kernel<<<dim3(64, NCHUNK), 256, SMEM_TOTAL>>>(ranks);
    combine_kernel<<<16, 256>>>(wf_b, out);
}

// round 12
// speedup vs baseline: 1.0374x; 1.0374x over previous
#include <cuda_runtime.h>
#include <cuda_fp16.h>
#include <cstdint>

// ============================================================================
// CAAN rank-gated attention (sm_100 base: mma.sync fp16 + cp.async):
//   Sf = fp16(S); f[i] = S[i].u + c (fused into convS, fp32)
//   Q,K = fp16( S Wq^T/Wk^T + b )  via single-product fp16 HMMA
//   gate2[d] = log2(e)/sqrt(128) * sigmoid(rank_emb[d].wL+bL)
//   p_ij = exp2( gate2[|ri-rj|/4] * (q_i.k_j) )   (no-max softmax; |arg| small)
//   out_i = sigmoid( (sum_j p f_j)/(sum_j p) + wf_b )
// R11 post-mortem: smem port binds (L1 60%); 4Mx2N quadrupled B redundancy so
// A-caching was a wash (256 ldsm4/tile both ways). R12: 2Mx4N (B redundancy
// 2) + A cached in 64 regs -> 128 ldsm4/tile, halved smem traffic.
// ============================================================================

#define N_ASSETS 4096
#define D_MODEL  512
#define DK       128
#define NUM_EMB  1024
#define NCHUNK   4
#define KEYS_PER_CHUNK (N_ASSETS / NCHUNK)
#define GATE_MUL    0.1275174677682657f      // (1/sqrt(128)) * log2(e)

typedef unsigned long long ull;

// --------------------------- scratch (no allocs) ----------------------------
__device__ __align__(16) __half d_Sf[N_ASSETS * D_MODEL];
__device__ __align__(16) __half d_Wf[256 * D_MODEL];   // rows 0-127 Wq, 128-255 Wk
__device__ __align__(16) __half d_Q[N_ASSETS * DK];
__device__ __align__(16) __half d_K[N_ASSETS * DK];
__device__ float d_f[N_ASSETS];
__device__ float d_u[D_MODEL + 1];
__device__ float d_gate[NUM_EMB];            // premultiplied by GATE_MUL
__device__ float d_pl[NCHUNK * N_ASSETS];
__device__ float d_pw[NCHUNK * N_ASSETS];

// --------------------------- mma/ldsm/cp.async helpers -----------------------
__device__ __forceinline__ uint32_t smem_u32(const void* p) {
    uint32_t a;
    asm("{ .reg .u64 t; cvta.to.shared.u64 t, %1; cvt.u32.u64 %0, t; }"
        : "=r"(a) : "l"(p));
    return a;
}
__device__ __forceinline__ void ldsm4(uint32_t* r, uint32_t addr) {
    asm volatile("ldmatrix.sync.aligned.m8n8.x4.shared.b16 {%0,%1,%2,%3}, [%4];"
                 : "=r"(r[0]), "=r"(r[1]), "=r"(r[2]), "=r"(r[3]) : "r"(addr));
}
__device__ __forceinline__ void mma_f16(float* c, const uint32_t* a, const uint32_t* b) {
    asm volatile(
        "mma.sync.aligned.m16n8k16.row.col.f32.f16.f16.f32 "
        "{%0,%1,%2,%3}, {%4,%5,%6,%7}, {%8,%9}, {%0,%1,%2,%3};"
        : "+f"(c[0]), "+f"(c[1]), "+f"(c[2]), "+f"(c[3])
        : "r"(a[0]), "r"(a[1]), "r"(a[2]), "r"(a[3]), "r"(b[0]), "r"(b[1]));
}
__device__ __forceinline__ void cp16(uint32_t dst, const void* src) {
    asm volatile("cp.async.cg.shared.global [%0], [%1], 16;" :: "r"(dst), "l"(src));
}
__device__ __forceinline__ void cp4(uint32_t dst, const void* src) {
    asm volatile("cp.async.ca.shared.global [%0], [%1], 4;" :: "r"(dst), "l"(src));
}
#define CP_COMMIT() asm volatile("cp.async.commit_group;" ::: "memory")
#define CP_WAIT0()  asm volatile("cp.async.wait_group 0;" ::: "memory")
#define CP_WAIT1()  asm volatile("cp.async.wait_group 1;" ::: "memory")

// XOR swizzle of 16B-chunk index within a 256B row (16 chunks)
__device__ __forceinline__ int swz(int chunk, int row) {
    return (chunk & 8) | ((chunk ^ row) & 7);
}

// ============================================================================
// prep: gate (b 0-3), u (b 4-19), c (b 20), W fp16 convert (b 21-84)
// ============================================================================
__global__ void prep_kernel(const float* __restrict__ rank_emb,
                            const float* __restrict__ wL_w,
                            const float* __restrict__ wL_b,
                            const float* __restrict__ Wv_w,
                            const float* __restrict__ wf_w,
                            const float* __restrict__ Wv_b,
                            const float* __restrict__ Wq_w,
                            const float* __restrict__ Wk_w) {
    int b = blockIdx.x, t = threadIdx.x;
    if (b < 4) {
        int d = b * 256 + t;
        float s = wL_b[0];
        #pragma unroll 8
        for (int e = 0; e < 32; e++) s += rank_emb[d * 32 + e] * wL_w[e];
        d_gate[d] = GATE_MUL / (1.0f + __expf(-s));
    } else if (b < 20) {
        int b2 = b - 4;
        int mloc = t & 31, oo = t >> 5;
        int m = b2 * 32 + mloc;
        float s = 0.f;
        #pragma unroll 4
        for (int o = oo; o < D_MODEL; o += 8) s += Wv_w[o * D_MODEL + m] * wf_w[o];
        __shared__ float red[256];
        red[t] = s; __syncthreads();
        if (t < 32) {
            float x = red[t];
            #pragma unroll
            for (int i = 1; i < 8; i++) x += red[t + 32 * i];
            d_u[m] = x;
        }
    } else if (b == 20) {
        __shared__ float red[256];
        float s = 0.f;
        for (int o = t; o < D_MODEL; o += 256) s += wf_w[o] * Wv_b[o];
        red[t] = s; __syncthreads();
        for (int st = 128; st > 0; st >>= 1) {
            if (t < st) red[t] += red[t + st];
            __syncthreads();
        }
        if (t == 0) d_u[D_MODEL] = red[0];
    } else {
        int g0 = (b - 21) * 2048 + t * 8;
        #pragma unroll
        for (int j = 0; j < 2; j++) {
            float4 v = (g0 + 4 * j < 65536)
                ? *(const float4*)(Wq_w + g0 + 4 * j)
                : *(const float4*)(Wk_w + g0 + 4 * j - 65536);
            __half2* dst = (__half2*)(d_Wf + g0 + 4 * j);
            dst[0] = __floats2half2_rn(v.x, v.y);
            dst[1] = __floats2half2_rn(v.z, v.w);
        }
    }
}

// ============================================================================
// convS: S -> fp16 AND f[i] = S[i].u + c (one pass)
// ============================================================================
__global__ void __launch_bounds__(256) convS_kernel(const float* __restrict__ S) {
    __shared__ float u_s[D_MODEL];
    int tid = threadIdx.x, w = tid >> 5, lane = tid & 31;
    #pragma unroll
    for (int t = 0; t < 2; t++) u_s[tid + 256 * t] = d_u[tid + 256 * t];
    __syncthreads();
    float c = d_u[D_MODEL];

    int rbase = blockIdx.x * 32 + w * 4;
    #pragma unroll
    for (int rr = 0; rr < 4; rr++) {
        int row = rbase + rr;
        const float2* src = (const float2*)(S + (size_t)row * D_MODEL);
        __half2* dst = (__half2*)(d_Sf + (size_t)row * D_MODEL);
        float s = 0.f;
        #pragma unroll
        for (int t = 0; t < 8; t++) {
            int e2 = lane + 32 * t;
            float2 v = src[e2];
            s += v.x * u_s[2 * e2] + v.y * u_s[2 * e2 + 1];
            dst[e2] = __floats2half2_rn(v.x, v.y);
        }
        #pragma unroll
        for (int st = 16; st > 0; st >>= 1)
            s += __shfl_xor_sync(0xffffffffu, s, st);
        if (lane == 0) d_f[row] = s + c;
    }
}

// ============================================================================
// proj_mma: Q/K = fp16( S @ W^T + b ) single-product fp16 HMMA, 2-stage pipe.
// grid (64 M-tiles of 64 rows, 2 = {Q,K}), 256 thr = 8 warps (2M x 4N).
// ============================================================================
#define PJ_BIAS 0           // 512B
#define PJ_STG  1024        // stage stride 49152: S 16K | W 32K
#define PJ_S    0
#define PJ_W    16384
#define PJ_TOTAL (1024 + 2 * 49152)

__device__ __forceinline__ void pj_copy_stage(uint32_t stg, int mbase, int by, int kc) {
    int tid = threadIdx.x;
    #pragma unroll
    for (int i = 0; i < 4; i++) {
        int idx = tid + 256 * i;
        int row = idx >> 4, c = idx & 15;
        const __half* g = d_Sf + (size_t)(mbase + row) * D_MODEL + kc * 128 + c * 8;
        cp16(stg + PJ_S + row * 256 + swz(c, row) * 16, g);
    }
    #pragma unroll
    for (int i = 0; i < 8; i++) {
        int idx = tid + 256 * i;
        int row = idx >> 4, c = idx & 15;
        const __half* g = d_Wf + (size_t)(by * 128 + row) * D_MODEL + kc * 128 + c * 8;
        cp16(stg + PJ_W + row * 256 + swz(c, row) * 16, g);
    }
}

__global__ void __launch_bounds__(256, 1) proj_mma_kernel(
    const float* __restrict__ Wq_b, const float* __restrict__ Wk_b) {
    extern __shared__ __align__(1024) char smem[];
    uint32_t sb = smem_u32(smem);
    float* bias_s = (float*)(smem + PJ_BIAS);

    int tid = threadIdx.x;
    int w = tid >> 5, lane = tid & 31;
    int wm = w >> 2, wn = w & 3;
    int mbase = blockIdx.x * 64;
    int by = blockIdx.y;                 // 0 = Q, 1 = K

    if (tid < 128) bias_s[tid] = (by ? Wk_b : Wq_b)[tid];

    float acc[2][4][4];
    #pragma unroll
    for (int mi = 0; mi < 2; mi++)
        #pragma unroll
        for (int nf = 0; nf < 4; nf++)
            #pragma unroll
            for (int e = 0; e < 4; e++) acc[mi][nf][e] = 0.f;

    int a_row  = lane & 15, a_hi = lane >> 4;
    int b_nloc = (lane & 7) | ((lane >> 1) & 8);
    int b_hi   = (lane >> 3) & 1;

    pj_copy_stage(sb + PJ_STG, mbase, by, 0);
    CP_COMMIT();

    for (int kc = 0; kc < 4; kc++) {
        uint32_t stg = sb + PJ_STG + (kc & 1) * 49152;
        if (kc < 3) {
            pj_copy_stage(sb + PJ_STG + ((kc + 1) & 1) * 49152, mbase, by, kc + 1);
            CP_COMMIT();
            CP_WAIT1();
        } else {
            CP_WAIT0();
        }
        __syncthreads();

        #pragma unroll
        for (int ks = 0; ks < 8; ks++) {
            uint32_t Bf[2][4];
            int cB = 2 * ks + b_hi;
            #pragma unroll
            for (int np = 0; np < 2; np++) {
                int nrow = wn * 32 + np * 16 + b_nloc;
                ldsm4(Bf[np], stg + PJ_W + nrow * 256 + swz(cB, nrow) * 16);
            }
            #pragma unroll
            for (int mi = 0; mi < 2; mi++) {
                uint32_t Af[4];
                int qrow = wm * 32 + mi * 16 + a_row;
                int cA = 2 * ks + a_hi;
                ldsm4(Af, stg + PJ_S + qrow * 256 + swz(cA, qrow) * 16);
                #pragma unroll
                for (int nf = 0; nf < 4; nf++)
                    mma_f16(acc[mi][nf], Af, &Bf[nf >> 1][(nf & 1) * 2]);
            }
        }
        __syncthreads();
    }

    __half* OUT = by ? d_K : d_Q;
    #pragma unroll
    for (int mi = 0; mi < 2; mi++)
        #pragma unroll
        for (int nf = 0; nf < 4; nf++)
            #pragma unroll
            for (int hrow = 0; hrow < 2; hrow++) {
                int row = mbase + wm * 32 + mi * 16 + (lane >> 2) + 8 * hrow;
                int col = wn * 32 + nf * 8 + 2 * (lane & 3);
                float v0 = acc[mi][nf][2 * hrow]     + bias_s[col];
                float v1 = acc[mi][nf][2 * hrow + 1] + bias_s[col + 1];
                *(__half2*)(OUT + (size_t)row * DK + col) = __floats2half2_rn(v0, v1);
            }
}

// ============================================================================
// attn: grid (64 qblocks of 64 rows, 4 chunks), 256 thr = 8 warps (2M x 4N),
// warp tile 32x32, Q fragments cached in 64 regs (B redundancy only 2 in this
// geometry -> per-tile smem reads halved to 128 ldsm4). Single acc set,
// epilogue after MMA per tile; K double-buffered; rk/fk 2-slot ring.
// ============================================================================
#define SM_GATE  0          // 4096
#define SM_RK    4096       // float[2][128] ring
#define SM_FK    5120
#define SM_PL    6144       // float[4][64]
#define SM_PW    7168
#define SM_Q     8192       // 16384
#define SM_K     24576      // 2 x 32768
#define SMEM_TOTAL 90112

__device__ __forceinline__ void cp_tile128(const __half* __restrict__ g,
                                           uint32_t st_base) {
    int tid = threadIdx.x;
    #pragma unroll
    for (int i = 0; i < 8; i++) {
        int idx = tid + 256 * i;
        int row = idx >> 4, c = idx & 15;
        cp16(st_base + row * 256 + swz(c, row) * 16, (const char*)g + row * 256 + c * 16);
    }
}
__device__ __forceinline__ void cp_tile64(const __half* __restrict__ g,
                                          uint32_t st_base) {
    int tid = threadIdx.x;
    #pragma unroll
    for (int i = 0; i < 4; i++) {
        int idx = tid + 256 * i;
        int row = idx >> 4, c = idx & 15;
        cp16(st_base + row * 256 + swz(c, row) * 16, (const char*)g + row * 256 + c * 16);
    }
}

__global__ void __launch_bounds__(256, 2) attn_kernel(const float* __restrict__ ranks) {
    extern __shared__ __align__(1024) char smem[];
    float* gate_s = (float*)(smem + SM_GATE);
    float* rk_s   = (float*)(smem + SM_RK);   // [2][128] ring
    float* fk_s   = (float*)(smem + SM_FK);
    float* pl_s   = (float*)(smem + SM_PL);   // [4][64]
    float* pw_s   = (float*)(smem + SM_PW);
    uint32_t sb = smem_u32(smem);

    int tid = threadIdx.x;
    int w = tid >> 5, lane = tid & 31;
    int wm = w >> 2, wn = w & 3;          // 2M x 4N warp grid, warp tile 32x32
    int qbase = blockIdx.x * 64;
    int cbase = blockIdx.y * KEYS_PER_CHUNK;

    #pragma unroll
    for (int t = 0; t < 4; t++) gate_s[tid + 256 * t] = d_gate[tid + 256 * t];

    cp_tile64(d_Q + (size_t)qbase * DK, sb + SM_Q);
    cp_tile128(d_K + (size_t)cbase * DK, sb + SM_K);
    if (tid < 128) {
        cp4(sb + SM_RK + tid * 4, ranks + cbase + tid);
        cp4(sb + SM_FK + tid * 4, d_f + cbase + tid);
    }
    CP_COMMIT();

    // per-thread rows: slot s = mi*2+h -> row = wm*32 + (s>>1)*16 + (lane>>2) + 8*(s&1)
    // pre-scaled by 0.25 (kills a FMUL per element; exact)
    float rq_t[4];
    #pragma unroll
    for (int s = 0; s < 4; s++)
        rq_t[s] = ranks[qbase + wm * 32 + (s >> 1) * 16 + (lane >> 2) + 8 * (s & 1)] * 0.25f;

    float l_t[4], w_t[4];
    #pragma unroll
    for (int s = 0; s < 4; s++) { l_t[s] = 0.f; w_t[s] = 0.f; }

    float acc[2][4][4];
    #pragma unroll
    for (int mi = 0; mi < 2; mi++)
        #pragma unroll
        for (int nf = 0; nf < 4; nf++)
            #pragma unroll
            for (int e = 0; e < 4; e++) acc[mi][nf][e] = 0.f;

    int a_row  = lane & 15, a_hi = lane >> 4;
    int b_nloc = (lane & 7) | ((lane >> 1) & 8);
    int b_hi   = (lane >> 3) & 1;
    int ccl    = 2 * (lane & 3);

    CP_WAIT0();
    __syncthreads();

    // ---- cache Q fragments in registers: reused for all 8 K-tiles ----
    uint32_t Af[2][8][4];
    #pragma unroll
    for (int mi = 0; mi < 2; mi++)
        #pragma unroll
        for (int ks = 0; ks < 8; ks++) {
            int qrow = wm * 32 + mi * 16 + a_row;
            int cA = 2 * ks + a_hi;
            ldsm4(Af[mi][ks], sb + SM_Q + qrow * 256 + swz(cA, qrow) * 16);
        }

    for (int kt = 0; kt < 8; kt++) {
        int buf = kt & 1;
        uint32_t Kb = sb + SM_K + buf * 32768;

        // prefetch next K tile into other buffer (overlaps MMA + epilogue)
        if (kt < 7) {
            int kb = cbase + (kt + 1) * 128;
            int nb = buf ^ 1;
            cp_tile128(d_K + (size_t)kb * DK, sb + SM_K + nb * 32768);
            if (tid < 128) {
                cp4(sb + SM_RK + (nb * 128 + tid) * 4, ranks + kb + tid);
                cp4(sb + SM_FK + (nb * 128 + tid) * 4, d_f + kb + tid);
            }
            CP_COMMIT();
        }

        // ---- MMA loop over k = 128 (B ldsm only; A from registers) ----
        #pragma unroll
        for (int ks = 0; ks < 8; ks++) {
            uint32_t Bf[2][4];
            int cB = 2 * ks + b_hi;
            #pragma unroll
            for (int np = 0; np < 2; np++) {
                int nrow = wn * 32 + np * 16 + b_nloc;
                ldsm4(Bf[np], Kb + nrow * 256 + swz(cB, nrow) * 16);
            }
            #pragma unroll
            for (int mi = 0; mi < 2; mi++)
                #pragma unroll
                for (int nf = 0; nf < 4; nf++)
                    mma_f16(acc[mi][nf], Af[mi][ks], &Bf[nf >> 1][(nf & 1) * 2]);
        }

        // ---- epilogue for tile kt (rk/fk ring slot kt&1; rk pre-scaled) ----
        {
            int es = kt & 1;
            float rk_t[8], fk_t[8];
            #pragma unroll
            for (int nf = 0; nf < 4; nf++)
                #pragma unroll
                for (int h = 0; h < 2; h++) {
                    int c = es * 128 + wn * 32 + nf * 8 + ccl + h;
                    rk_t[nf * 2 + h] = rk_s[c] * 0.25f;
                    fk_t[nf * 2 + h] = fk_s[c];
                }
            #pragma unroll
            for (int mi = 0; mi < 2; mi++)
                #pragma unroll
                for (int nf = 0; nf < 4; nf++)
                    #pragma unroll
                    for (int e = 0; e < 4; e++) {
                        int s = mi * 2 + (e >> 1);
                        int ci = nf * 2 + (e & 1);
                        int di = __float2int_rd(fabsf(rq_t[s] - rk_t[ci]));
                        float pr = exp2f(gate_s[di] * acc[mi][nf][e]);
                        l_t[s] += pr;
                        w_t[s] += pr * fk_t[ci];
                        acc[mi][nf][e] = 0.f;
                    }
        }

        CP_WAIT0();
        __syncthreads();
    }

    // quad reduce (cols within warp), then across 4 N-warps via smem
    #pragma unroll
    for (int s = 0; s < 4; s++) {
        #pragma unroll
        for (int st = 1; st < 4; st <<= 1) {
            l_t[s] += __shfl_xor_sync(0xffffffffu, l_t[s], st);
            w_t[s] += __shfl_xor_sync(0xffffffffu, w_t[s], st);
        }
    }
    if ((lane & 3) == 0) {
        #pragma unroll
        for (int s = 0; s < 4; s++) {
            int row = wm * 32 + (s >> 1) * 16 + (lane >> 2) + 8 * (s & 1);
            pl_s[wn * 64 + row] = l_t[s];
            pw_s[wn * 64 + row] = w_t[s];
        }
    }
    __syncthreads();
    if (tid < 64) {
        float L = 0.f, W = 0.f;
        #pragma unroll
        for (int k = 0; k < 4; k++) {
            L += pl_s[k * 64 + tid];
            W += pw_s[k * 64 + tid];
        }
        int idx = blockIdx.y * N_ASSETS + qbase + tid;
        d_pl[idx] = L;
        d_pw[idx] = W;
    }
}

// ============================================================================
// combine: merge NCHUNK partial sums, final sigmoid
// ============================================================================
__global__ void combine_kernel(const float* __restrict__ wf_b, float* __restrict__ out) {
    int i = blockIdx.x * blockDim.x + threadIdx.x;
    if (i >= N_ASSETS) return;
    float L = 0.f, W = 0.f;
    #pragma unroll
    for (int c = 0; c < NCHUNK; c++) {
        L += d_pl[c * N_ASSETS + i];
        W += d_pw[c * N_ASSETS + i];
    }
    float z = W / L + wf_b[0];
    out[i] = 1.0f / (1.0f + __expf(-z));
}

// ============================================================================
// launch
// ============================================================================
extern "C" void kernel_launch(void* const* d_in, const int* in_sizes, int n_in,
                              void* d_out, int out_size) {
    const float* S        = (const float*)d_in[0];
    const float* ranks    = (const float*)d_in[1];
    const float* Wq_w     = (const float*)d_in[2];
    const float* Wq_b     = (const float*)d_in[3];
    const float* Wk_w     = (const float*)d_in[4];
    const float* Wk_b     = (const float*)d_in[5];
    const float* Wv_w     = (const float*)d_in[6];
    const float* Wv_b     = (const float*)d_in[7];
    const float* rank_emb = (const float*)d_in[8];
    const float* wL_w     = (const float*)d_in[9];
    const float* wL_b     = (const float*)d_in[10];
    const float* wf_w     = (const float*)d_in[11];
    const float* wf_b     = (const float*)d_in[12];
    float* out = (float*)d_out;

    static int attr_set = 0;
    if (!attr_set) {
        cudaFuncSetAttribute(attn_kernel,
                             cudaFuncAttributeMaxDynamicSharedMemorySize, SMEM_TOTAL);
        cudaFuncSetAttribute(proj_mma_kernel,
                             cudaFuncAttributeMaxDynamicSharedMemorySize, PJ_TOTAL);
        attr_set = 1;
    }

    prep_kernel<<<85, 256>>>(rank_emb, wL_w, wL_b, Wv_w, wf_w, Wv_b, Wq_w, Wk_w);
    convS_kernel<<<128, 256>>>(S);
    proj_mma_kernel<<<dim3(64, 2), 256, PJ_TOTAL>>>(Wq_b, Wk_b);
    attn_kernel<<<dim3(64, NCHUNK), 256, SMEM_TOTAL>>>(ranks);
    combine_kernel<<<16, 256>>>(wf_b, out);
}